// round 16
// baseline (speedup 1.0000x reference)
#include <cuda_runtime.h>
#include <cuda_fp16.h>
#include <cuda_bf16.h>

// Problem constants
#define RR 8
#define NN 40000
#define FF 128           // F_IN == F_OUT == 128
#define EE 160000
#define NEDGES (RR * EE) // 1,280,000

#define PAD 96           // padded slots per node (mean degree 32, 11-sigma slack)

#define GEMM_NB ((NN + 127) / 128)        // 313
#define FILL_NB (NEDGES / 4 / 256)        // 1250

// Scratch (__device__ globals; zero-initialized at load; no allocations)
__device__ __half g_yh[NN * FF];        // ent_mat @ weight_ent, fp16 (10 MB)
__device__ float  g_alpha[RR];
__device__ int    g_cnt[NN];            // fill cursor; gather reads then re-zeros
__device__ int2   g_pedge[NN * PAD];    // payload: {dst, coef bits}

// ---------------------------------------------------------------------------
// GEMM: C[128 rows/block] = fp16( A @ B ), f32x2 packed FMA inner
// ---------------------------------------------------------------------------
__global__ __launch_bounds__(256) void gemm_kernel(const float* __restrict__ A,
                                                   const float* __restrict__ B,
                                                   __half* __restrict__ C) {
    __shared__ float As_[8 * 128];
    __shared__ float Bs_[8 * 128];
    int m0 = blockIdx.x * 128;
    int tid = threadIdx.x;
    int row_t = tid >> 4;   // 0..15
    int col_t = tid & 15;   // 0..15

    unsigned long long acc2[8][4];
#pragma unroll
    for (int i = 0; i < 8; i++)
#pragma unroll
        for (int j = 0; j < 4; j++) acc2[i][j] = 0ull;

    int a_row = tid >> 1;        // 0..127
    int a_k4  = (tid & 1) * 4;   // 0 or 4
    int b_kk  = tid >> 5;        // 0..7
    int b_c4  = (tid & 31) * 4;  // 0..124

    for (int k0 = 0; k0 < 128; k0 += 8) {
        float4 av = make_float4(0.f, 0.f, 0.f, 0.f);
        int grow = m0 + a_row;
        if (grow < NN) av = *(const float4*)(A + (long)grow * FF + k0 + a_k4);
        As_[(a_k4 + 0) * 128 + a_row] = av.x;
        As_[(a_k4 + 1) * 128 + a_row] = av.y;
        As_[(a_k4 + 2) * 128 + a_row] = av.z;
        As_[(a_k4 + 3) * 128 + a_row] = av.w;
        *(float4*)(&Bs_[b_kk * 128 + b_c4]) = *(const float4*)(B + (k0 + b_kk) * FF + b_c4);
        __syncthreads();
#pragma unroll
        for (int kk = 0; kk < 8; kk++) {
            float a[8], b[8];
            *(float4*)(a)     = *(const float4*)(&As_[kk * 128 + row_t * 8]);
            *(float4*)(a + 4) = *(const float4*)(&As_[kk * 128 + row_t * 8 + 4]);
            *(float4*)(b)     = *(const float4*)(&Bs_[kk * 128 + col_t * 8]);
            *(float4*)(b + 4) = *(const float4*)(&Bs_[kk * 128 + col_t * 8 + 4]);
            unsigned long long b2[4];
#pragma unroll
            for (int jp = 0; jp < 4; jp++) {
                asm("mov.b64 %0, {%1, %2};"
                    : "=l"(b2[jp]) : "f"(b[2 * jp]), "f"(b[2 * jp + 1]));
            }
#pragma unroll
            for (int i = 0; i < 8; i++) {
                unsigned long long a2;
                asm("mov.b64 %0, {%1, %1};" : "=l"(a2) : "f"(a[i]));
#pragma unroll
                for (int jp = 0; jp < 4; jp++) {
                    asm("fma.rn.f32x2 %0, %1, %2, %0;"
                        : "+l"(acc2[i][jp]) : "l"(a2), "l"(b2[jp]));
                }
            }
        }
        __syncthreads();
    }

#pragma unroll
    for (int i = 0; i < 8; i++) {
        int grow = m0 + row_t * 8 + i;
        if (grow < NN) {
            __half2 hc[4];
#pragma unroll
            for (int jp = 0; jp < 4; jp++) {
                float2 f;
                asm("mov.b64 {%0, %1}, %2;" : "=f"(f.x), "=f"(f.y) : "l"(acc2[i][jp]));
                hc[jp] = __float22half2_rn(f);
            }
            *(uint4*)(C + (long)grow * FF + col_t * 8) = *(uint4*)hc;
        }
    }
}

// ---------------------------------------------------------------------------
// Alpha + tail: 1 block, 256 threads. f-outer, 8 independent FMA chains.
// Stream-ordered before fill (same stream) -> no flag needed.
// ---------------------------------------------------------------------------
__global__ __launch_bounds__(256) void alpha_kernel(const float* __restrict__ rel_mat,
                                                    const float* __restrict__ w1,
                                                    const float* __restrict__ b1,
                                                    const float* __restrict__ w2,
                                                    float* __restrict__ out) {
    __shared__ float rel_s[RR * FF];
    __shared__ float h[RR * FF];
    int o = threadIdx.x;
    // tail copy: 1024 floats = 256 float4, one per thread
    ((float4*)(out + (long)NN * FF))[o] = ((const float4*)rel_mat)[o];

    if (o < 128) {
#pragma unroll
        for (int r = 0; r < RR; r++) rel_s[r * FF + o] = rel_mat[r * FF + o];
    }
    __syncthreads();
    if (o < 128) {
        float accs[RR];
#pragma unroll
        for (int r = 0; r < RR; r++) accs[r] = b1[o];
#pragma unroll 8
        for (int f = 0; f < FF; f++) {
            float w = __ldg(w1 + f * FF + o);
#pragma unroll
            for (int r = 0; r < RR; r++) accs[r] += rel_s[r * FF + f] * w;
        }
        float w2o = w2[o];
#pragma unroll
        for (int r = 0; r < RR; r++) h[r * FF + o] = tanhf(accs[r]) * w2o;
    }
    __syncthreads();
    for (int s = 64; s > 0; s >>= 1) {
        if (o < s) {
#pragma unroll
            for (int r = 0; r < RR; r++) h[r * FF + o] += h[r * FF + o + s];
        }
        __syncthreads();
    }
    if (o < RR) {
        float z = h[o * FF];
        g_alpha[o] = 1.0f / (1.0f + expf(-z));
    }
}

// ---------------------------------------------------------------------------
// Fill: standalone (lean registers, high occupancy). 4 edges/thread.
// ---------------------------------------------------------------------------
__global__ __launch_bounds__(256) void fill_kernel(const int* __restrict__ edge_src,
                                                   const int* __restrict__ edge_dst,
                                                   const float* __restrict__ edge_val) {
    int q = blockIdx.x * blockDim.x + threadIdx.x;   // quad index
    if (q >= NEDGES / 4) return;
    int4   s4 = __ldg((const int4*)edge_src + q);
    int4   d4 = __ldg((const int4*)edge_dst + q);
    float4 v4 = __ldg((const float4*)edge_val + q);
    int r = q / (EE / 4);   // EE divisible by 4: quad never straddles relations
    float al = g_alpha[r];

    int p0 = atomicAdd(&g_cnt[s4.x], 1);
    int p1 = atomicAdd(&g_cnt[s4.y], 1);
    int p2 = atomicAdd(&g_cnt[s4.z], 1);
    int p3 = atomicAdd(&g_cnt[s4.w], 1);
    g_pedge[s4.x * PAD + p0] = make_int2(d4.x, __float_as_int(al * v4.x));
    g_pedge[s4.y * PAD + p1] = make_int2(d4.y, __float_as_int(al * v4.y));
    g_pedge[s4.z * PAD + p2] = make_int2(d4.z, __float_as_int(al * v4.z));
    g_pedge[s4.w * PAD + p3] = make_int2(d4.w, __float_as_int(al * v4.w));
}

// ---------------------------------------------------------------------------
// Gather: one warp per node; 8-deep independent load batch (R12-proven).
// 128-thread blocks, (128,9): 36 resident warps/SM at the same 54-reg codegen.
// ---------------------------------------------------------------------------
#define GATHER_NB (NN * 32 / 128)   // 10000

__global__ __launch_bounds__(128, 9) void gather_kernel(float* __restrict__ out) {
    int warp = (blockIdx.x * blockDim.x + threadIdx.x) >> 5;
    int lane = threadIdx.x & 31;
    if (warp >= NN) return;

    int cnt = g_cnt[warp];
    int s = warp * PAD;
    int e = s + cnt;

    float4 acc = make_float4(0.f, 0.f, 0.f, 0.f);
    int i = s;
    // 8 edges per iteration: 4 int4 payload loads + 8 independent y-row loads
    for (; i + 7 < e; i += 8) {
        int4 pa = __ldg((const int4*)(g_pedge + i));      // {dst0,c0,dst1,c1}
        int4 pb = __ldg((const int4*)(g_pedge + i + 2));
        int4 pc = __ldg((const int4*)(g_pedge + i + 4));
        int4 pd = __ldg((const int4*)(g_pedge + i + 6));
        uint2 r0 = __ldg((const uint2*)(g_yh + (long)pa.x * FF) + lane);
        uint2 r1 = __ldg((const uint2*)(g_yh + (long)pa.z * FF) + lane);
        uint2 r2 = __ldg((const uint2*)(g_yh + (long)pb.x * FF) + lane);
        uint2 r3 = __ldg((const uint2*)(g_yh + (long)pb.z * FF) + lane);
        uint2 r4 = __ldg((const uint2*)(g_yh + (long)pc.x * FF) + lane);
        uint2 r5 = __ldg((const uint2*)(g_yh + (long)pc.z * FF) + lane);
        uint2 r6 = __ldg((const uint2*)(g_yh + (long)pd.x * FF) + lane);
        uint2 r7 = __ldg((const uint2*)(g_yh + (long)pd.z * FF) + lane);
        float c0 = __int_as_float(pa.y), c1 = __int_as_float(pa.w);
        float c2 = __int_as_float(pb.y), c3 = __int_as_float(pb.w);
        float c4 = __int_as_float(pc.y), c5 = __int_as_float(pc.w);
        float c6 = __int_as_float(pd.y), c7 = __int_as_float(pd.w);
        float2 a0 = __half22float2(*(__half2*)&r0.x), b0 = __half22float2(*(__half2*)&r0.y);
        float2 a1 = __half22float2(*(__half2*)&r1.x), b1 = __half22float2(*(__half2*)&r1.y);
        float2 a2 = __half22float2(*(__half2*)&r2.x), b2 = __half22float2(*(__half2*)&r2.y);
        float2 a3 = __half22float2(*(__half2*)&r3.x), b3 = __half22float2(*(__half2*)&r3.y);
        float2 a4 = __half22float2(*(__half2*)&r4.x), b4 = __half22float2(*(__half2*)&r4.y);
        float2 a5 = __half22float2(*(__half2*)&r5.x), b5 = __half22float2(*(__half2*)&r5.y);
        float2 a6 = __half22float2(*(__half2*)&r6.x), b6 = __half22float2(*(__half2*)&r6.y);
        float2 a7 = __half22float2(*(__half2*)&r7.x), b7 = __half22float2(*(__half2*)&r7.y);
        acc.x += c0 * a0.x + c1 * a1.x + c2 * a2.x + c3 * a3.x
               + c4 * a4.x + c5 * a5.x + c6 * a6.x + c7 * a7.x;
        acc.y += c0 * a0.y + c1 * a1.y + c2 * a2.y + c3 * a3.y
               + c4 * a4.y + c5 * a5.y + c6 * a6.y + c7 * a7.y;
        acc.z += c0 * b0.x + c1 * b1.x + c2 * b2.x + c3 * b3.x
               + c4 * b4.x + c5 * b5.x + c6 * b6.x + c7 * b7.x;
        acc.w += c0 * b0.y + c1 * b1.y + c2 * b2.y + c3 * b3.y
               + c4 * b4.y + c5 * b5.y + c6 * b6.y + c7 * b7.y;
    }
    for (; i < e; i++) {
        int2 p0 = __ldg(g_pedge + i);
        uint2 r0 = __ldg((const uint2*)(g_yh + (long)p0.x * FF) + lane);
        float c0 = __int_as_float(p0.y);
        float2 a0 = __half22float2(*(__half2*)&r0.x), b0 = __half22float2(*(__half2*)&r0.y);
        acc.x += c0 * a0.x;
        acc.y += c0 * a0.y;
        acc.z += c0 * b0.x;
        acc.w += c0 * b0.y;
    }
    ((float4*)(out + (long)warp * FF))[lane] = acc;

    // restore launch invariant (after the hot loop)
    if (lane == 0) g_cnt[warp] = 0;
}

// ---------------------------------------------------------------------------
// Launch: fork-join streams so fill (lean regs, high occ) truly co-schedules
// with gemm (fat regs). Stream/events created once on the first call
// (the correctness run — before graph capture); capture sees only
// record/wait/launch nodes, which are capturable.
// ---------------------------------------------------------------------------
extern "C" void kernel_launch(void* const* d_in, const int* in_sizes, int n_in,
                              void* d_out, int out_size) {
    const float* ent_mat    = (const float*)d_in[0];
    const float* rel_mat    = (const float*)d_in[1];
    const int*   edge_src   = (const int*)d_in[2];
    const int*   edge_dst   = (const int*)d_in[3];
    const float* edge_val   = (const float*)d_in[4];
    const float* weight_ent = (const float*)d_in[5];
    const float* proj_w1    = (const float*)d_in[6];
    const float* proj_b1    = (const float*)d_in[7];
    const float* proj_w2    = (const float*)d_in[8];
    float* out = (float*)d_out;

    static cudaStream_t s1 = nullptr;
    static cudaEvent_t ev_fork = nullptr, ev_join = nullptr;
    if (s1 == nullptr) {
        cudaStreamCreateWithFlags(&s1, cudaStreamNonBlocking);
        cudaEventCreateWithFlags(&ev_fork, cudaEventDisableTiming);
        cudaEventCreateWithFlags(&ev_join, cudaEventDisableTiming);
    }

    __half* yh;
    cudaGetSymbolAddress((void**)&yh, g_yh);

    // fork: gemm on side stream
    cudaEventRecord(ev_fork, 0);
    cudaStreamWaitEvent(s1, ev_fork, 0);
    gemm_kernel<<<GEMM_NB, 256, 0, s1>>>(ent_mat, weight_ent, yh);
    cudaEventRecord(ev_join, s1);

    // default stream: alpha -> fill (stream-ordered)
    alpha_kernel<<<1, 256>>>(rel_mat, proj_w1, proj_b1, proj_w2, out);
    fill_kernel<<<FILL_NB, 256>>>(edge_src, edge_dst, edge_val);

    // join, then gather
    cudaStreamWaitEvent(0, ev_join, 0);
    gather_kernel<<<GATHER_NB, 128>>>(out);
}

// round 17
// speedup vs baseline: 1.0891x; 1.0891x over previous
#include <cuda_runtime.h>
#include <cuda_fp16.h>
#include <cuda_bf16.h>

// Problem constants
#define RR 8
#define NN 40000
#define FF 128           // F_IN == F_OUT == 128
#define EE 160000
#define NEDGES (RR * EE) // 1,280,000

#define PAD 96           // padded slots per node (mean degree 32, 11-sigma slack)

#define GEMM_NB ((NN + 127) / 128)        // 313
#define FILL_NB (NEDGES / 4 / 256)        // 1250
#define K1_NB   (1 + GEMM_NB + FILL_NB)   // alpha+tail block, gemm, fill

// Scratch (__device__ globals; zero-initialized at load; no allocations)
__device__ __half g_yh[NN * FF];        // ent_mat @ weight_ent, fp16 (10 MB)
__device__ float  g_alpha[RR];
__device__ int    g_alpha_ready;        // release flag; gather resets to 0
__device__ int    g_cnt[NN];            // fill cursor; gather reads then re-zeros
__device__ int2   g_pedge[NN * PAD];    // payload: {dst, coef bits}

// ---------------------------------------------------------------------------
// GEMM block body: C[128 rows @ m0] = fp16( A @ B ), f32x2 packed FMA inner
// ---------------------------------------------------------------------------
__device__ __forceinline__ void gemm_block(int m0,
                                           const float* __restrict__ A,
                                           const float* __restrict__ B,
                                           __half* __restrict__ C,
                                           float* __restrict__ As_,   // [8][128]
                                           float* __restrict__ Bs_) { // [8][128]
    int tid = threadIdx.x;
    int row_t = tid >> 4;   // 0..15
    int col_t = tid & 15;   // 0..15

    unsigned long long acc2[8][4];
#pragma unroll
    for (int i = 0; i < 8; i++)
#pragma unroll
        for (int j = 0; j < 4; j++) acc2[i][j] = 0ull;

    int a_row = tid >> 1;        // 0..127
    int a_k4  = (tid & 1) * 4;   // 0 or 4
    int b_kk  = tid >> 5;        // 0..7
    int b_c4  = (tid & 31) * 4;  // 0..124

    for (int k0 = 0; k0 < 128; k0 += 8) {
        float4 av = make_float4(0.f, 0.f, 0.f, 0.f);
        int grow = m0 + a_row;
        if (grow < NN) av = *(const float4*)(A + (long)grow * FF + k0 + a_k4);
        As_[(a_k4 + 0) * 128 + a_row] = av.x;
        As_[(a_k4 + 1) * 128 + a_row] = av.y;
        As_[(a_k4 + 2) * 128 + a_row] = av.z;
        As_[(a_k4 + 3) * 128 + a_row] = av.w;
        *(float4*)(&Bs_[b_kk * 128 + b_c4]) = *(const float4*)(B + (k0 + b_kk) * FF + b_c4);
        __syncthreads();
#pragma unroll
        for (int kk = 0; kk < 8; kk++) {
            float a[8], b[8];
            *(float4*)(a)     = *(const float4*)(&As_[kk * 128 + row_t * 8]);
            *(float4*)(a + 4) = *(const float4*)(&As_[kk * 128 + row_t * 8 + 4]);
            *(float4*)(b)     = *(const float4*)(&Bs_[kk * 128 + col_t * 8]);
            *(float4*)(b + 4) = *(const float4*)(&Bs_[kk * 128 + col_t * 8 + 4]);
            unsigned long long b2[4];
#pragma unroll
            for (int jp = 0; jp < 4; jp++) {
                asm("mov.b64 %0, {%1, %2};"
                    : "=l"(b2[jp]) : "f"(b[2 * jp]), "f"(b[2 * jp + 1]));
            }
#pragma unroll
            for (int i = 0; i < 8; i++) {
                unsigned long long a2;
                asm("mov.b64 %0, {%1, %1};" : "=l"(a2) : "f"(a[i]));
#pragma unroll
                for (int jp = 0; jp < 4; jp++) {
                    asm("fma.rn.f32x2 %0, %1, %2, %0;"
                        : "+l"(acc2[i][jp]) : "l"(a2), "l"(b2[jp]));
                }
            }
        }
        __syncthreads();
    }

#pragma unroll
    for (int i = 0; i < 8; i++) {
        int grow = m0 + row_t * 8 + i;
        if (grow < NN) {
            __half2 hc[4];
#pragma unroll
            for (int jp = 0; jp < 4; jp++) {
                float2 f;
                asm("mov.b64 {%0, %1}, %2;" : "=f"(f.x), "=f"(f.y) : "l"(acc2[i][jp]));
                hc[jp] = __float22half2_rn(f);
            }
            *(uint4*)(C + (long)grow * FF + col_t * 8) = *(uint4*)hc;
        }
    }
}

// ---------------------------------------------------------------------------
// Alpha + tail block: f-outer loop, 8 independent FMA chains per thread.
// Publishes g_alpha then releases g_alpha_ready. Also copies rel_mat tail.
// ---------------------------------------------------------------------------
__device__ __forceinline__ void alpha_tail_block(const float* __restrict__ rel_mat,
                                                 const float* __restrict__ w1,
                                                 const float* __restrict__ b1,
                                                 const float* __restrict__ w2,
                                                 float* __restrict__ out,
                                                 float* __restrict__ rel_s,  // [1024]
                                                 float* __restrict__ h) {    // [1024]
    int o = threadIdx.x;
    // tail copy: 1024 floats = 256 float4, one per thread
    ((float4*)(out + (long)NN * FF))[o] = ((const float4*)rel_mat)[o];

    if (o < 128) {
#pragma unroll
        for (int r = 0; r < RR; r++) rel_s[r * FF + o] = rel_mat[r * FF + o];
    }
    __syncthreads();
    if (o < 128) {
        float accs[RR];
#pragma unroll
        for (int r = 0; r < RR; r++) accs[r] = b1[o];
#pragma unroll 8
        for (int f = 0; f < FF; f++) {
            float w = __ldg(w1 + f * FF + o);
#pragma unroll
            for (int r = 0; r < RR; r++) accs[r] += rel_s[r * FF + f] * w;
        }
        float w2o = w2[o];
#pragma unroll
        for (int r = 0; r < RR; r++) h[r * FF + o] = tanhf(accs[r]) * w2o;
    }
    __syncthreads();
    for (int s = 64; s > 0; s >>= 1) {
        if (o < s) {
#pragma unroll
            for (int r = 0; r < RR; r++) h[r * FF + o] += h[r * FF + o + s];
        }
        __syncthreads();
    }
    if (o < RR) {
        float z = h[o * FF];
        g_alpha[o] = 1.0f / (1.0f + expf(-z));
    }
    __syncthreads();
    if (o == 0) {
        __threadfence();                       // release: alpha visible first
        atomicExch(&g_alpha_ready, 1);
    }
}

// ---------------------------------------------------------------------------
// K1: block 0 = alpha+tail; blocks 1..GEMM_NB = GEMM; rest = fill.
// Fill blocks acquire-spin on g_alpha_ready (block 0 is wave-1 resident).
// (R12-proven layout; measured 48.6us.)
// ---------------------------------------------------------------------------
__global__ __launch_bounds__(256) void k1_kernel(const float* __restrict__ ent_mat,
                                                 const float* __restrict__ weight_ent,
                                                 const int* __restrict__ edge_src,
                                                 const int* __restrict__ edge_dst,
                                                 const float* __restrict__ edge_val,
                                                 const float* __restrict__ rel_mat,
                                                 const float* __restrict__ w1,
                                                 const float* __restrict__ b1,
                                                 const float* __restrict__ w2,
                                                 float* __restrict__ out) {
    __shared__ float sh0[8 * 128];
    __shared__ float sh1[8 * 128];
    int bx = blockIdx.x;
    if (bx == 0) {
        alpha_tail_block(rel_mat, w1, b1, w2, out, sh0, sh1);
    } else if (bx <= GEMM_NB) {
        gemm_block((bx - 1) * 128, ent_mat, weight_ent, g_yh, sh0, sh1);
    } else {
        // acquire: wait for alpha
        if (threadIdx.x == 0) {
            while (atomicAdd(&g_alpha_ready, 0) == 0) { }
        }
        __syncthreads();   // all threads ordered after the acquire

        int q = (bx - 1 - GEMM_NB) * 256 + threadIdx.x;   // quad index
        if (q >= NEDGES / 4) return;
        int4   s4 = __ldg((const int4*)edge_src + q);
        int4   d4 = __ldg((const int4*)edge_dst + q);
        float4 v4 = __ldg((const float4*)edge_val + q);
        int r = q / (EE / 4);   // EE divisible by 4: quad never straddles relations
        float al = g_alpha[r];

        int p0 = atomicAdd(&g_cnt[s4.x], 1);
        int p1 = atomicAdd(&g_cnt[s4.y], 1);
        int p2 = atomicAdd(&g_cnt[s4.z], 1);
        int p3 = atomicAdd(&g_cnt[s4.w], 1);
        g_pedge[s4.x * PAD + p0] = make_int2(d4.x, __float_as_int(al * v4.x));
        g_pedge[s4.y * PAD + p1] = make_int2(d4.y, __float_as_int(al * v4.y));
        g_pedge[s4.z * PAD + p2] = make_int2(d4.z, __float_as_int(al * v4.z));
        g_pedge[s4.w * PAD + p3] = make_int2(d4.w, __float_as_int(al * v4.w));
    }
}

// ---------------------------------------------------------------------------
// K2: gather (R15-measured form: 37.9us). One warp per node; 8-deep
// independent load batch; 128-thread blocks at (128,9) -> 36 warps/SM.
// ---------------------------------------------------------------------------
#define GATHER_NB (NN * 32 / 128)   // 10000

__global__ __launch_bounds__(128, 9) void gather_kernel(float* __restrict__ out) {
    int warp = (blockIdx.x * blockDim.x + threadIdx.x) >> 5;
    int lane = threadIdx.x & 31;
    if (warp >= NN) return;

    int cnt = g_cnt[warp];
    int s = warp * PAD;
    int e = s + cnt;

    float4 acc = make_float4(0.f, 0.f, 0.f, 0.f);
    int i = s;
    // 8 edges per iteration: 4 int4 payload loads + 8 independent y-row loads
    for (; i + 7 < e; i += 8) {
        int4 pa = __ldg((const int4*)(g_pedge + i));      // {dst0,c0,dst1,c1}
        int4 pb = __ldg((const int4*)(g_pedge + i + 2));
        int4 pc = __ldg((const int4*)(g_pedge + i + 4));
        int4 pd = __ldg((const int4*)(g_pedge + i + 6));
        uint2 r0 = __ldg((const uint2*)(g_yh + (long)pa.x * FF) + lane);
        uint2 r1 = __ldg((const uint2*)(g_yh + (long)pa.z * FF) + lane);
        uint2 r2 = __ldg((const uint2*)(g_yh + (long)pb.x * FF) + lane);
        uint2 r3 = __ldg((const uint2*)(g_yh + (long)pb.z * FF) + lane);
        uint2 r4 = __ldg((const uint2*)(g_yh + (long)pc.x * FF) + lane);
        uint2 r5 = __ldg((const uint2*)(g_yh + (long)pc.z * FF) + lane);
        uint2 r6 = __ldg((const uint2*)(g_yh + (long)pd.x * FF) + lane);
        uint2 r7 = __ldg((const uint2*)(g_yh + (long)pd.z * FF) + lane);
        float c0 = __int_as_float(pa.y), c1 = __int_as_float(pa.w);
        float c2 = __int_as_float(pb.y), c3 = __int_as_float(pb.w);
        float c4 = __int_as_float(pc.y), c5 = __int_as_float(pc.w);
        float c6 = __int_as_float(pd.y), c7 = __int_as_float(pd.w);
        float2 a0 = __half22float2(*(__half2*)&r0.x), b0 = __half22float2(*(__half2*)&r0.y);
        float2 a1 = __half22float2(*(__half2*)&r1.x), b1 = __half22float2(*(__half2*)&r1.y);
        float2 a2 = __half22float2(*(__half2*)&r2.x), b2 = __half22float2(*(__half2*)&r2.y);
        float2 a3 = __half22float2(*(__half2*)&r3.x), b3 = __half22float2(*(__half2*)&r3.y);
        float2 a4 = __half22float2(*(__half2*)&r4.x), b4 = __half22float2(*(__half2*)&r4.y);
        float2 a5 = __half22float2(*(__half2*)&r5.x), b5 = __half22float2(*(__half2*)&r5.y);
        float2 a6 = __half22float2(*(__half2*)&r6.x), b6 = __half22float2(*(__half2*)&r6.y);
        float2 a7 = __half22float2(*(__half2*)&r7.x), b7 = __half22float2(*(__half2*)&r7.y);
        acc.x += c0 * a0.x + c1 * a1.x + c2 * a2.x + c3 * a3.x
               + c4 * a4.x + c5 * a5.x + c6 * a6.x + c7 * a7.x;
        acc.y += c0 * a0.y + c1 * a1.y + c2 * a2.y + c3 * a3.y
               + c4 * a4.y + c5 * a5.y + c6 * a6.y + c7 * a7.y;
        acc.z += c0 * b0.x + c1 * b1.x + c2 * b2.x + c3 * b3.x
               + c4 * b4.x + c5 * b5.x + c6 * b6.x + c7 * b7.x;
        acc.w += c0 * b0.y + c1 * b1.y + c2 * b2.y + c3 * b3.y
               + c4 * b4.y + c5 * b5.y + c6 * b6.y + c7 * b7.y;
    }
    for (; i < e; i++) {
        int2 p0 = __ldg(g_pedge + i);
        uint2 r0 = __ldg((const uint2*)(g_yh + (long)p0.x * FF) + lane);
        float c0 = __int_as_float(p0.y);
        float2 a0 = __half22float2(*(__half2*)&r0.x), b0 = __half22float2(*(__half2*)&r0.y);
        acc.x += c0 * a0.x;
        acc.y += c0 * a0.y;
        acc.z += c0 * b0.x;
        acc.w += c0 * b0.y;
    }
    ((float4*)(out + (long)warp * FF))[lane] = acc;

    // restore launch invariants (after the hot loop)
    if (lane == 0) g_cnt[warp] = 0;
    if (warp == 0 && lane == 1) g_alpha_ready = 0;
}

// ---------------------------------------------------------------------------
extern "C" void kernel_launch(void* const* d_in, const int* in_sizes, int n_in,
                              void* d_out, int out_size) {
    const float* ent_mat    = (const float*)d_in[0];
    const float* rel_mat    = (const float*)d_in[1];
    const int*   edge_src   = (const int*)d_in[2];
    const int*   edge_dst   = (const int*)d_in[3];
    const float* edge_val   = (const float*)d_in[4];
    const float* weight_ent = (const float*)d_in[5];
    const float* proj_w1    = (const float*)d_in[6];
    const float* proj_b1    = (const float*)d_in[7];
    const float* proj_w2    = (const float*)d_in[8];
    float* out = (float*)d_out;

    // K1: alpha+tail (block 0) || gemm || fill (fill acquires alpha via flag)
    k1_kernel<<<K1_NB, 256>>>(ent_mat, weight_ent, edge_src, edge_dst, edge_val,
                              rel_mat, proj_w1, proj_b1, proj_w2, out);

    // K2: gather (8-deep MLP, 128-thread blocks; restores invariants)
    gather_kernel<<<GATHER_NB, 128>>>(out);
}